// round 16
// baseline (speedup 1.0000x reference)
#include <cuda_runtime.h>

// NTM memory module. B=2048, N=512, U=64.
// R11 = R9/R10 two-kernel split + Programmatic Dependent Launch overlap.
//   A1: memory -> logits (coalesced 16-thr/row, barrier-free). Triggers PDL.
//   B': launched with ProgrammaticStreamSerialization. Pre-sync: prefetch
//       first triad tile + e/a/w_pre/scalars (independent of A1). Then
//       cudaGridDependencySynchronize() -> logits -> w -> 79%-DRAM triad.
// Overlap hides A1's ragged tail + the kernel-boundary bubble.

#define BB 2048
#define NN 512
#define UU 64
#define THREADS 256
#define NWARPS (THREADS / 32)

__device__ __forceinline__ float warpSum(float v) {
    #pragma unroll
    for (int o = 16; o > 0; o >>= 1) v += __shfl_down_sync(0xffffffffu, v, o);
    return v;
}
__device__ __forceinline__ float blockSum(float v, float* s_red, int lane, int wid) {
    __syncthreads();
    v = warpSum(v);
    if (lane == 0) s_red[wid] = v;
    __syncthreads();
    if (wid == 0) {
        float x = (lane < NWARPS) ? s_red[lane] : 0.0f;
        x = warpSum(x);
        if (lane == 0) s_red[0] = x;
    }
    __syncthreads();
    return s_red[0];
}

// ---------------- A1: logits only, barrier-free stream ----------------
__global__ void __launch_bounds__(THREADS) ntm_logits_kernel(
    const float* __restrict__ memory,   // (B,N,U)
    const float* __restrict__ kvec,     // (B,U)
    const float* __restrict__ beta_p,
    float* __restrict__ out_logits)     // (B,N)  (out_w used as scratch)
{
    __shared__ float s_k[UU];

    const int b  = blockIdx.x;
    const int t  = threadIdx.x;
    const int c  = t & 15;               // float4 chunk within row (0..15)
    const int rg = t >> 4;               // row within 16-row group

    const float beta = beta_p[0];
    const float4* mem4 = reinterpret_cast<const float4*>(memory + (size_t)b * NN * UU);

    if (t < UU) s_k[t] = kvec[b * UU + t];   // +1e-16 is an fp32 no-op here
    __syncthreads();

    float ny2 = 0.0f;
    {
        const float4* k4p = reinterpret_cast<const float4*>(s_k);
        #pragma unroll
        for (int i = 0; i < UU / 4; i++) {
            float4 kk = k4p[i];
            ny2 += kk.x * kk.x + kk.y * kk.y + kk.z * kk.z + kk.w * kk.w;
        }
    }
    const float ny = fmaxf(sqrtf(ny2), 1e-8f);
    const float binv = beta / ny;
    const float4 k4 = reinterpret_cast<const float4*>(s_k)[c];

    float* logits_b = out_logits + (size_t)b * NN;

    #pragma unroll
    for (int ii = 0; ii < 4; ii++) {
        float4 v[8];
        #pragma unroll
        for (int j = 0; j < 8; j++)
            v[j] = __ldg(mem4 + (ii * 8 + j) * THREADS + t);
        #pragma unroll
        for (int j = 0; j < 8; j++) {
            float dot = v[j].x * k4.x + v[j].y * k4.y + v[j].z * k4.z + v[j].w * k4.w;
            float nrm = v[j].x * v[j].x + v[j].y * v[j].y
                      + v[j].z * v[j].z + v[j].w * v[j].w;
            #pragma unroll
            for (int o = 8; o > 0; o >>= 1) {
                dot += __shfl_down_sync(0xffffffffu, dot, o, 16);
                nrm += __shfl_down_sync(0xffffffffu, nrm, o, 16);
            }
            if (c == 0) {
                float nx = fmaxf(sqrtf(nrm), 1e-8f);
                logits_b[(ii * 8 + j) * 16 + rg] = binv * dot / nx;
            }
        }
    }

    // Allow the dependent kernel's CTAs to start launching (their pre-sync
    // prefetch overlaps this kernel's drain). Grid-sync in B' still waits
    // for ALL of this kernel's stores to complete.
    cudaTriggerProgrammaticLaunchCompletion();
}

// -------- B': PDL prologue + softmax/gate/shift/sharpen + triad --------
__global__ void __launch_bounds__(THREADS) ntm_rw_kernel(
    const float* __restrict__ memory,   // (B,N,U)
    const float* __restrict__ e_p,      // (B,U)
    const float* __restrict__ a_p,      // (B,U)
    const float* __restrict__ g_p,
    const float* __restrict__ s_p,      // (B,3)
    const float* __restrict__ gamma_p,
    const float* __restrict__ w_pre,    // (B,N)
    float* __restrict__ out_w,          // (B,N)  in: logits, out: final w
    float* __restrict__ out_r,          // (B,U)
    float* __restrict__ out_mem)        // (B,N,U)
{
    __shared__ float s_wg[NN];
    __shared__ float s_w[NN];
    __shared__ float s_red[32];
    __shared__ float4 s_part[THREADS];

    const int b    = blockIdx.x;
    const int t    = threadIdx.x;
    const int lane = t & 31;
    const int wid  = t >> 5;
    const int c    = t & 15;
    const int rg   = t >> 4;

    const float4* mem4 = reinterpret_cast<const float4*>(memory + (size_t)b * NN * UU);
    float4*       out4 = reinterpret_cast<float4*>(out_mem + (size_t)b * NN * UU);

    // ---- pre-sync work: everything independent of A1's logits ----
    float4 v0[4];
    #pragma unroll
    for (int j = 0; j < 4; j++) v0[j] = __ldcs(mem4 + j * THREADS + t);
    float4 e4 = __ldg(reinterpret_cast<const float4*>(e_p + (size_t)b * UU) + c);
    float4 a4 = __ldg(reinterpret_cast<const float4*>(a_p + (size_t)b * UU) + c);
    const float g     = g_p[0];
    const float gamma = gamma_p[0];
    const float s0 = s_p[b * 3 + 0];
    const float s1 = s_p[b * 3 + 1];
    const float s2 = s_p[b * 3 + 2];
    const float wp0 = w_pre[(size_t)b * NN + t];
    const float wp1 = w_pre[(size_t)b * NN + t + THREADS];

    // ---- wait for A1 (all logits stores visible) ----
    cudaGridDependencySynchronize();

    if (t < NN / 4)
        reinterpret_cast<float4*>(s_wg)[t] =
            __ldg(reinterpret_cast<const float4*>(out_w + (size_t)b * NN) + t);
    __syncthreads();

    // softmax (no max subtraction: |logit| <= beta) + gate
    {
        float p0 = __expf(s_wg[t]);
        float p1 = __expf(s_wg[t + THREADS]);
        float ps = blockSum(p0 + p1, s_red, lane, wid);
        float inv = 1.0f / ps;
        s_wg[t]           = (p0 * inv) * g + (1.0f - g) * wp0;
        s_wg[t + THREADS] = (p1 * inv) * g + (1.0f - g) * wp1;
    }
    __syncthreads();

    // circular shift + sharpen + renormalize -> final w
    {
        float wpw0, wpw1;
        {
            int n = t;
            int nm1 = (n == 0) ? NN - 1 : n - 1;
            float ws = s0 * s_wg[nm1] + s1 * s_wg[n] + s2 * s_wg[n + 1];
            wpw0 = (gamma == 2.0f) ? ws * ws : powf(ws, gamma);
        }
        {
            int n = t + THREADS;
            int np1 = (n == NN - 1) ? 0 : n + 1;
            float ws = s0 * s_wg[n - 1] + s1 * s_wg[n] + s2 * s_wg[np1];
            wpw1 = (gamma == 2.0f) ? ws * ws : powf(ws, gamma);
        }
        float tot = blockSum(wpw0 + wpw1, s_red, lane, wid);
        float inv = 1.0f / tot;
        float w0 = wpw0 * inv + 1e-16f;
        float w1 = wpw1 * inv + 1e-16f;
        s_w[t]           = w0;
        s_w[t + THREADS] = w1;
        out_w[(size_t)b * NN + t]           = w0;
        out_w[(size_t)b * NN + t + THREADS] = w1;
    }
    __syncthreads();

    // barrier-free triad (first tile from pre-sync prefetch regs)
    float4 racc = make_float4(0.f, 0.f, 0.f, 0.f);
    #pragma unroll
    for (int j = 0; j < 4; j++) {
        float wn = s_w[j * 16 + rg];
        racc.x += wn * v0[j].x;
        racc.y += wn * v0[j].y;
        racc.z += wn * v0[j].z;
        racc.w += wn * v0[j].w;
        float4 o;
        o.x = v0[j].x * (1.0f - wn * e4.x) + wn * a4.x;
        o.y = v0[j].y * (1.0f - wn * e4.y) + wn * a4.y;
        o.z = v0[j].z * (1.0f - wn * e4.z) + wn * a4.z;
        o.w = v0[j].w * (1.0f - wn * e4.w) + wn * a4.w;
        __stcs(out4 + j * THREADS + t, o);
    }
    #pragma unroll
    for (int ii = 1; ii < 8; ii++) {
        float4 v[4];
        #pragma unroll
        for (int j = 0; j < 4; j++)
            v[j] = __ldcs(mem4 + (ii * 4 + j) * THREADS + t);
        #pragma unroll
        for (int j = 0; j < 4; j++) {
            float wn = s_w[(ii * 4 + j) * 16 + rg];
            racc.x += wn * v[j].x;
            racc.y += wn * v[j].y;
            racc.z += wn * v[j].z;
            racc.w += wn * v[j].w;
            float4 o;
            o.x = v[j].x * (1.0f - wn * e4.x) + wn * a4.x;
            o.y = v[j].y * (1.0f - wn * e4.y) + wn * a4.y;
            o.z = v[j].z * (1.0f - wn * e4.z) + wn * a4.z;
            o.w = v[j].w * (1.0f - wn * e4.w) + wn * a4.w;
            __stcs(out4 + (ii * 4 + j) * THREADS + t, o);
        }
    }
    s_part[rg * 16 + c] = racc;
    __syncthreads();
    if (t < 16) {
        float4 acc = make_float4(0.f, 0.f, 0.f, 0.f);
        #pragma unroll
        for (int j = 0; j < 16; j++) {
            float4 p = s_part[j * 16 + t];
            acc.x += p.x; acc.y += p.y; acc.z += p.z; acc.w += p.w;
        }
        reinterpret_cast<float4*>(out_r + (size_t)b * UU)[t] = acc;
    }
}

extern "C" void kernel_launch(void* const* d_in, const int* in_sizes, int n_in,
                              void* d_out, int out_size) {
    const float* memory  = (const float*)d_in[0];
    const float* kvec    = (const float*)d_in[1];
    const float* beta_p  = (const float*)d_in[2];
    const float* g_p     = (const float*)d_in[3];
    const float* s_p     = (const float*)d_in[4];
    const float* gamma_p = (const float*)d_in[5];
    const float* w_pre   = (const float*)d_in[6];
    const float* e_p     = (const float*)d_in[7];
    const float* a_p     = (const float*)d_in[8];

    float* out_w   = (float*)d_out;                       // B*N
    float* out_r   = out_w + (size_t)BB * NN;             // B*U
    float* out_mem = out_r + (size_t)BB * UU;             // B*N*U

    ntm_logits_kernel<<<BB, THREADS>>>(memory, kvec, beta_p, out_w);

    // Dependent launch with programmatic (PDL) overlap.
    cudaLaunchConfig_t cfg = {};
    cfg.gridDim  = dim3(BB, 1, 1);
    cfg.blockDim = dim3(THREADS, 1, 1);
    cfg.dynamicSmemBytes = 0;
    cudaLaunchAttribute attrs[1];
    attrs[0].id = cudaLaunchAttributeProgrammaticStreamSerialization;
    attrs[0].val.programmaticStreamSerializationAllowed = 1;
    cfg.attrs = attrs;
    cfg.numAttrs = 1;
    cudaLaunchKernelEx(&cfg, ntm_rw_kernel,
                       memory, e_p, a_p, g_p, s_p, gamma_p,
                       w_pre, out_w, out_r, out_mem);
}